// round 5
// baseline (speedup 1.0000x reference)
#include <cuda_runtime.h>
#include <cuda_bf16.h>
#include <cstdint>

#define Hn    250       // hidden units
#define Bn    256       // batch
#define Tn    512       // time steps
#define Gn    1000      // 4*H gate rows
#define HP    256       // padded hidden stride (elements)
#define KP    252       // padded K for recurrent GEMM
#define KCn   63        // KP/4 chunks

// ---------------- scratch (device globals; zero-initialized at load) ----------------
__device__ float              g_xg[(size_t)Tn * Bn * Gn];          // input-gate contributions
__device__ float              g_h1[(size_t)(Tn + 1) * Bn * HP];    // layer-0 h (plain), slice 0 zeros
__device__ float              g_h2[(size_t)(Tn + 1) * Bn * HP];    // layer-1 h (plain)
__device__ unsigned long long g_hd[(size_t)(Tn + 1) * Bn * HP];    // duplicated {h,h} pairs (both layers reuse)
__device__ unsigned           g_cnt [2][8][32];                    // per-(layer, batch-group) arrive counters, line-padded
__device__ unsigned           g_flag[2][8][32];                    // per-(layer, batch-group) epoch flags

// ---------------- helpers ----------------
__device__ __forceinline__ float sigf(float x) { return 1.f / (1.f + __expf(-x)); }
__device__ __forceinline__ float tanhfast(float x) { return 1.f - 2.f / (__expf(2.f * x) + 1.f); }

__device__ __forceinline__ unsigned long long pack2(float lo, float hi) {
    unsigned long long r;
    asm("mov.b64 %0, {%1, %2};" : "=l"(r) : "f"(lo), "f"(hi));
    return r;
}
__device__ __forceinline__ void unpack2(unsigned long long v, float& lo, float& hi) {
    asm("mov.b64 {%0, %1}, %2;" : "=f"(lo), "=f"(hi) : "l"(v));
}
__device__ __forceinline__ void ffma2(unsigned long long& acc, unsigned long long a, unsigned long long b) {
    asm("fma.rn.f32x2 %0, %1, %2, %0;" : "+l"(acc) : "l"(a), "l"(b));
}

// Transposed, gate-interleaved weight tile: sW[k*64 + m], m = u_local*4 + g.
__device__ void fill_WT(float* sW, const float* __restrict__ W, int u0, int Kreal, int kc_n) {
    int total = 64 * kc_n;
    for (int i = threadIdx.x; i < total; i += blockDim.x) {
        int m  = i / kc_n;
        int kc = i - m * kc_n;
        int k  = kc * 4;
        int g  = m & 3;
        int u  = u0 + (m >> 2);
        float4 v = make_float4(0.f, 0.f, 0.f, 0.f);
        if (u < Hn) {
            const float* src = W + (size_t)(g * Hn + u) * Kreal + k;
            if (k + 0 < Kreal) v.x = src[0];
            if (k + 1 < Kreal) v.y = src[1];
            if (k + 2 < Kreal) v.z = src[2];
            if (k + 3 < Kreal) v.w = src[3];
        }
        sW[(k + 0) * 64 + m] = v.x;
        sW[(k + 1) * 64 + m] = v.y;
        sW[(k + 2) * 64 + m] = v.z;
        sW[(k + 3) * 64 + m] = v.w;
    }
}

__global__ void k_reset() {
    unsigned* c = &g_cnt[0][0][0];
    unsigned* f = &g_flag[0][0][0];
    for (int i = threadIdx.x; i < 2 * 8 * 32; i += blockDim.x) { c[i] = 0u; f[i] = 0u; }
}

// ---------------- input-contribution GEMM (f32x2) ----------------
__global__ void __launch_bounds__(256, 1)
k_xgemm(const float* __restrict__ A_in, const float* __restrict__ Wih,
        const float* __restrict__ bih, const float* __restrict__ bhh,
        int amode, int Kreal, int kc_n) {
    extern __shared__ float smem[];
    float* sW = smem;                       // kc_n*4 * 64
    float* sA = sW + (size_t)kc_n * 4 * 64; // 64 * 260
    float* sB = sA + 64 * 260;              // 64 bias
    int tid = threadIdx.x;
    int u0 = blockIdx.y * 16;
    int rbase = blockIdx.x * 64;

    fill_WT(sW, Wih, u0, Kreal, kc_n);
    if (tid < 64) {
        int g = tid & 3, u = u0 + (tid >> 2);
        sB[tid] = (u < Hn) ? (bih[g * Hn + u] + bhh[g * Hn + u]) : 0.f;
    }
    if (amode == 1) {
        const float4* src = (const float4*)(g_h1 + ((size_t)rbase + Bn) * HP);
        for (int i = tid; i < 64 * 64; i += 256) {
            int row = i >> 6, c4 = i & 63;
            *(float4*)&sA[row * 260 + c4 * 4] = __ldg(src + (size_t)row * 64 + c4);
        }
    } else {
        for (int i = tid; i < 64 * 10; i += 256) {
            int row = i / 10, c4 = i - row * 10;
            int r = rbase + row;
            int tt = r >> 8, b = r & 255;
            *(float4*)&sA[row * 260 + c4 * 4] =
                __ldg((const float4*)(A_in + ((size_t)b * Tn + tt) * 40 + c4 * 4));
        }
    }
    __syncthreads();

    int q = tid & 15, rg = tid >> 4;
    int rl = rg * 4;
    unsigned long long a0_if = 0ull, a0_go = 0ull, a1_if = 0ull, a1_go = 0ull;
    unsigned long long a2_if = 0ull, a2_go = 0ull, a3_if = 0ull, a3_go = 0ull;

    #pragma unroll 3
    for (int kc = 0; kc < kc_n; ++kc) {
        int k = kc * 4;
        ulonglong2 w0 = *(const ulonglong2*)&sW[(k + 0) * 64 + 4 * q];
        ulonglong2 w1 = *(const ulonglong2*)&sW[(k + 1) * 64 + 4 * q];
        ulonglong2 w2 = *(const ulonglong2*)&sW[(k + 2) * 64 + 4 * q];
        ulonglong2 w3 = *(const ulonglong2*)&sW[(k + 3) * 64 + 4 * q];
#define XACC(AIF, AGO, ROW)                                                          \
        {                                                                            \
            float4 av = *(const float4*)&sA[(rl + ROW) * 260 + k];                   \
            unsigned long long h0 = pack2(av.x, av.x);                               \
            unsigned long long h1 = pack2(av.y, av.y);                               \
            unsigned long long h2 = pack2(av.z, av.z);                               \
            unsigned long long h3 = pack2(av.w, av.w);                               \
            ffma2(AIF, w0.x, h0); ffma2(AGO, w0.y, h0);                              \
            ffma2(AIF, w1.x, h1); ffma2(AGO, w1.y, h1);                              \
            ffma2(AIF, w2.x, h2); ffma2(AGO, w2.y, h2);                              \
            ffma2(AIF, w3.x, h3); ffma2(AGO, w3.y, h3);                              \
        }
        XACC(a0_if, a0_go, 0) XACC(a1_if, a1_go, 1) XACC(a2_if, a2_go, 2) XACC(a3_if, a3_go, 3)
#undef XACC
    }

    int u = u0 + q;
    if (u < Hn) {
        float4 bv = *(const float4*)&sB[4 * q];
#define XOUT(AIF, AGO, ROW)                                                          \
        {                                                                            \
            float4 o; float lo, hi;                                                  \
            unpack2(AIF, lo, hi); o.x = lo + bv.x; o.y = hi + bv.y;                  \
            unpack2(AGO, lo, hi); o.z = lo + bv.z; o.w = hi + bv.w;                  \
            *(float4*)(g_xg + ((size_t)(rbase + rl + ROW)) * Gn + u * 4) = o;        \
        }
        XOUT(a0_if, a0_go, 0) XOUT(a1_if, a1_go, 1) XOUT(a2_if, a2_go, 2) XOUT(a3_if, a3_go, 3)
#undef XOUT
    }
}

// ---------------- persistent recurrent kernel ----------------
// 128 CTAs = 16 unit-tiles x 8 batch-groups. Thread: unit q = tid&15, batch cols c0,c0+1.
// h read pre-packed {h,h} from L2 (g_hd) with a depth-4 software pipeline; W from smem.
__global__ void __launch_bounds__(256, 1)
k_rec(const float* __restrict__ Whh, int layer) {
    extern __shared__ float smem[];
    float* sW = smem;   // KP*64 floats

    float* hplain = layer ? g_h2 : g_h1;
    const float* xg = g_xg;

    int tid = threadIdx.x, lane = tid & 31;
    int ut = blockIdx.x & 15, bt = blockIdx.x >> 4;
    int u0 = ut * 16, b0 = bt * 32;
    int q = tid & 15, cg = tid >> 4, c0 = cg * 2;
    int u = u0 + q;
    bool valid = (u < Hn);

    unsigned* cnt = &g_cnt[layer][bt][0];
    unsigned* flg = &g_flag[layer][bt][0];

    fill_WT(sW, Whh, u0, Hn, KCn);

    float cv0 = 0.f, cv1 = 0.f;
    __syncthreads();   // sW ready (read-only afterwards)

    for (int t = 0; t < Tn; ++t) {
        const unsigned long long* rowA = g_hd + ((size_t)t * Bn + b0 + c0) * HP;
        const unsigned long long* rowB = rowA + HP;

        // prefetch xg contributions for this step (DRAM latency hidden under GEMM)
        float4 x0 = make_float4(0.f, 0.f, 0.f, 0.f), x1 = x0;
        if (valid) {
            size_t r0 = (size_t)t * Bn + b0 + c0;
            x0 = __ldg((const float4*)(xg + r0 * Gn + u * 4));
            x1 = __ldg((const float4*)(xg + (r0 + 1) * Gn + u * 4));
        }

        unsigned long long A_if = 0ull, A_go = 0ull, B_if = 0ull, B_go = 0ull;

        // depth-4 pipelined h loads from L2 (packed {h,h}); tail loads past kc=62 hit the
        // in-bounds dummy chunk 63 region (KP pad inside HP=256 row) and are never used.
#define HLOAD(S, KC)                                                                 \
        ulonglong2 a##S##lo, a##S##hi, b##S##lo, b##S##hi;                           \
        a##S##lo = __ldcg((const ulonglong2*)(rowA + (KC) * 4));                     \
        a##S##hi = __ldcg((const ulonglong2*)(rowA + (KC) * 4 + 2));                 \
        b##S##lo = __ldcg((const ulonglong2*)(rowB + (KC) * 4));                     \
        b##S##hi = __ldcg((const ulonglong2*)(rowB + (KC) * 4 + 2));
#define HRELOAD(S, KC)                                                               \
        a##S##lo = __ldcg((const ulonglong2*)(rowA + (KC) * 4));                     \
        a##S##hi = __ldcg((const ulonglong2*)(rowA + (KC) * 4 + 2));                 \
        b##S##lo = __ldcg((const ulonglong2*)(rowB + (KC) * 4));                     \
        b##S##hi = __ldcg((const ulonglong2*)(rowB + (KC) * 4 + 2));
#define HCOMP(S, KC)                                                                 \
        {                                                                            \
            ulonglong2 w0 = *(const ulonglong2*)&sW[((KC) * 4 + 0) * 64 + 4 * q];    \
            ulonglong2 w1 = *(const ulonglong2*)&sW[((KC) * 4 + 1) * 64 + 4 * q];    \
            ulonglong2 w2 = *(const ulonglong2*)&sW[((KC) * 4 + 2) * 64 + 4 * q];    \
            ulonglong2 w3 = *(const ulonglong2*)&sW[((KC) * 4 + 3) * 64 + 4 * q];    \
            ffma2(A_if, w0.x, a##S##lo.x); ffma2(A_go, w0.y, a##S##lo.x);            \
            ffma2(A_if, w1.x, a##S##lo.y); ffma2(A_go, w1.y, a##S##lo.y);            \
            ffma2(A_if, w2.x, a##S##hi.x); ffma2(A_go, w2.y, a##S##hi.x);            \
            ffma2(A_if, w3.x, a##S##hi.y); ffma2(A_go, w3.y, a##S##hi.y);            \
            ffma2(B_if, w0.x, b##S##lo.x); ffma2(B_go, w0.y, b##S##lo.x);            \
            ffma2(B_if, w1.x, b##S##lo.y); ffma2(B_go, w1.y, b##S##lo.y);            \
            ffma2(B_if, w2.x, b##S##hi.x); ffma2(B_go, w2.y, b##S##hi.x);            \
            ffma2(B_if, w3.x, b##S##hi.y); ffma2(B_go, w3.y, b##S##hi.y);            \
        }

        HLOAD(0, 0) HLOAD(1, 1) HLOAD(2, 2) HLOAD(3, 3)

        #pragma unroll 1
        for (int kc = 0; kc < 60; kc += 4) {
            HCOMP(0, kc + 0) HRELOAD(0, kc + 4)
            HCOMP(1, kc + 1) HRELOAD(1, kc + 5)
            HCOMP(2, kc + 2) HRELOAD(2, kc + 6)
            HCOMP(3, kc + 3) HRELOAD(3, kc + 7)   // kc=56 iter loads kc 60..63; 63 is a safe dummy
        }
        HCOMP(0, 60) HCOMP(1, 61) HCOMP(2, 62)
#undef HLOAD
#undef HRELOAD
#undef HCOMP

        // pointwise LSTM cells
        {
            float gi, gf, gg, go;
            unpack2(A_if, gi, gf); unpack2(A_go, gg, go);
            float iv = sigf(gi + x0.x);
            float fv = sigf(gf + x0.y);
            float gv = tanhfast(gg + x0.z);
            float ov = sigf(go + x0.w);
            cv0 = fv * cv0 + iv * gv;
            float hv = ov * tanhfast(cv0);
            if (valid) {
                size_t w = ((size_t)(t + 1) * Bn + b0 + c0) * HP + u;
                __stcg(hplain + w, hv);
                __stcg((unsigned long long*)(g_hd + w), pack2(hv, hv));
            }
        }
        {
            float gi, gf, gg, go;
            unpack2(B_if, gi, gf); unpack2(B_go, gg, go);
            float iv = sigf(gi + x1.x);
            float fv = sigf(gf + x1.y);
            float gv = tanhfast(gg + x1.z);
            float ov = sigf(go + x1.w);
            cv1 = fv * cv1 + iv * gv;
            float hv = ov * tanhfast(cv1);
            if (valid) {
                size_t w = ((size_t)(t + 1) * Bn + b0 + c0 + 1) * HP + u;
                __stcg(hplain + w, hv);
                __stcg((unsigned long long*)(g_hd + w), pack2(hv, hv));
            }
        }

        // ---- 16-CTA batch-group barrier (sense-epoch) ----
        unsigned epoch = (unsigned)(t + 1);
        __threadfence();       // order h stores before arrival
        __syncthreads();
        if (tid == 0) {
            unsigned old = atomicAdd(cnt, 1u);
            if (old == 15u) {
                atomicExch(cnt, 0u);
                asm volatile("st.release.gpu.b32 [%0], %1;" :: "l"(flg), "r"(epoch) : "memory");
            }
        }
        if (lane == 0) {
            unsigned v;
            do {
                asm volatile("ld.acquire.gpu.b32 %0, [%1];" : "=r"(v) : "l"(flg) : "memory");
            } while (v < epoch);
        }
        __syncwarp();
    }
}

// ---------------- output head ----------------
__global__ void __launch_bounds__(256, 1)
k_head(const float* __restrict__ Wl, const float* __restrict__ bl, float* __restrict__ out) {
    __shared__ float sw[256];
    int tid = threadIdx.x;
    sw[tid] = (tid < Hn) ? Wl[tid] : 0.f;
    __syncthreads();
    int warp = tid >> 5, lane = tid & 31;
    int r = blockIdx.x * 8 + warp;          // r = b*T + t
    int t = r & (Tn - 1);
    int b = r >> 9;
    const float* hrow = g_h2 + ((size_t)(t + 1) * Bn + b) * HP;
    float p = 0.f;
    #pragma unroll
    for (int j = 0; j < 8; ++j) {
        int k = j * 32 + lane;
        p = fmaf(sw[k], __ldg(hrow + k), p);
    }
    #pragma unroll
    for (int off = 16; off; off >>= 1) p += __shfl_xor_sync(0xffffffffu, p, off);
    if (lane == 0) out[r] = 1.f / (1.f + __expf(-(p + bl[0])));
}

// ---------------- launcher ----------------
extern "C" void kernel_launch(void* const* d_in, const int* in_sizes, int n_in,
                              void* d_out, int out_size) {
    const float* x    = (const float*)d_in[0];
    const float* Wih0 = (const float*)d_in[1];
    const float* Whh0 = (const float*)d_in[2];
    const float* bih0 = (const float*)d_in[3];
    const float* bhh0 = (const float*)d_in[4];
    const float* Wih1 = (const float*)d_in[5];
    const float* Whh1 = (const float*)d_in[6];
    const float* bih1 = (const float*)d_in[7];
    const float* bhh1 = (const float*)d_in[8];
    const float* Wlin = (const float*)d_in[9];
    const float* blin = (const float*)d_in[10];
    float* out = (float*)d_out;

    const int smem_rec   = (KP * 64) * 4;                          // 64,512 B
    const int smem_gemm1 = (KCn * 4 * 64 + 64 * 260 + 64) * 4;     // 131,328 B
    const int smem_gemm0 = (10 * 4 * 64 + 64 * 260 + 64) * 4;      // 77,056 B

    cudaFuncSetAttribute(k_rec,   cudaFuncAttributeMaxDynamicSharedMemorySize, smem_rec);
    cudaFuncSetAttribute(k_xgemm, cudaFuncAttributeMaxDynamicSharedMemorySize, smem_gemm1);

    k_reset<<<1, 256>>>();

    // layer 0
    k_xgemm<<<dim3(2048, 16), 256, smem_gemm0>>>(x, Wih0, bih0, bhh0, 0, 40, 10);
    k_rec<<<128, 256, smem_rec>>>(Whh0, 0);

    // layer 1
    k_xgemm<<<dim3(2048, 16), 256, smem_gemm1>>>(nullptr, Wih1, bih1, bhh1, 1, Hn, KCn);
    k_rec<<<128, 256, smem_rec>>>(Whh1, 1);

    // head
    k_head<<<16384, 256>>>(Wlin, blin, out);
}